// round 13
// baseline (speedup 1.0000x reference)
#include <cuda_runtime.h>
#include <cstdint>

static constexpr int kNUsers = 100000;
static constexpr int kNItems = 500000;
static constexpr int kDim    = 64;
static constexpr int kNScore = 256;

static constexpr int ITILE  = 32;                    // 500000 % 32 == 0
static constexpr int NTILES = kNItems / ITILE;       // 15625 exact
static constexpr int PITCH  = 68;                    // floats per row; 272 B, 16B-aligned

// ---- SMEM layout (float offsets) ----
static constexpr int OF_USQ = 0;                     // 256
static constexpr int OF_ISQ = 256;                   // 2 x 32 (double buffered)
static constexpr int OF_U   = 320;                   // 256*68 (startup staging)
static constexpr int OF_I   = OF_U + 256 * PITCH;    // 17728
static constexpr int IBUF   = ITILE * PITCH;         // 2176 floats per buffer
static constexpr int SMEM_FLOATS = OF_I + 2 * IBUF;  // 22080
static constexpr unsigned SMEM_BYTES = SMEM_FLOATS * 4;   // 88320 -> 2 CTAs/SM

__device__ __forceinline__ uint32_t smem_u32(const void* p) {
    return (uint32_t)__cvta_generic_to_shared(p);
}
__device__ __forceinline__ uint32_t f2tf32(float x) {
    uint32_t r;
    asm("cvt.rna.tf32.f32 %0, %1;" : "=r"(r) : "f"(x));
    return r;
}
__device__ __forceinline__ float rsum16(float sq) {
    sq += __shfl_xor_sync(0xffffffffu, sq, 1);
    sq += __shfl_xor_sync(0xffffffffu, sq, 2);
    sq += __shfl_xor_sync(0xffffffffu, sq, 4);
    sq += __shfl_xor_sync(0xffffffffu, sq, 8);
    return sq;
}
#define LDMX4(q, addr)                                                         \
    asm volatile("ldmatrix.sync.aligned.m8n8.x4.shared.b16 {%0,%1,%2,%3}, [%4];" \
                 : "=r"((q)[0]), "=r"((q)[1]), "=r"((q)[2]), "=r"((q)[3])      \
                 : "r"(addr))
#define CP_ASYNC16(dst, src)                                                   \
    asm volatile("cp.async.cg.shared.global [%0], [%1], 16;"                   \
                 :: "r"(dst), "l"(src) : "memory")
#define CP_COMMIT()  asm volatile("cp.async.commit_group;" ::: "memory")
#define CP_WAIT0()   asm volatile("cp.async.wait_group 0;" ::: "memory")

__global__ void __launch_bounds__(256, 2)
cml_kernel(const int* __restrict__ ids,
           const float* __restrict__ users,
           const float* __restrict__ items,
           float* __restrict__ out)
{
    extern __shared__ float smem[];
    float* usq = smem + OF_USQ;
    float* sU  = smem + OF_U;

    const int tid  = threadIdx.x;
    const int lane = tid & 31;
    const int w    = tid >> 5;    // warp id -> users w*32 .. w*32+31
    const int c    = tid & 15;    // float4 chunk within 64-dim row
    const int r0   = tid >> 4;    // staging row (users)
    const int g    = lane >> 2;   // mma groupID
    const int t    = lane & 3;    // mma threadID-in-group
    const int uw   = w * 32;

    // ---- stage all 256 users: exact fp32 u_sq, rna-tf32 operand ----
    #pragma unroll
    for (int rr = 0; rr < 16; rr++) {
        const int r = r0 + rr * 16;
        const int uid = ids[r];
        float4 v = reinterpret_cast<const float4*>(users)[(size_t)uid * (kDim / 4) + c];
        float sq = rsum16(fmaf(v.x, v.x, fmaf(v.y, v.y, fmaf(v.z, v.z, v.w * v.w))));
        if (c == 0) usq[r] = sq;
        reinterpret_cast<uint4*>(sU + r * PITCH)[c] =
            make_uint4(f2tf32(v.x), f2tf32(v.y), f2tf32(v.z), f2tf32(v.w));
    }
    __syncthreads();

    // ---- hoist A fragments (this warp's 32 users, all k) into registers, forever ----
    uint32_t Af[2][8][4];
    #pragma unroll
    for (int mb = 0; mb < 2; mb++) {
        #pragma unroll
        for (int kb = 0; kb < 8; kb++) {
            const uint32_t* ap = reinterpret_cast<const uint32_t*>(
                sU + (uw + mb * 16 + g) * PITCH + kb * 8 + t);
            Af[mb][kb][0] = ap[0];
            Af[mb][kb][1] = ap[8 * PITCH];
            Af[mb][kb][2] = ap[4];
            Af[mb][kb][3] = ap[8 * PITCH + 4];
        }
    }
    float uqr[2][2];
    #pragma unroll
    for (int mb = 0; mb < 2; mb++) {
        uqr[mb][0] = usq[uw + mb * 16 + g];
        uqr[mb][1] = usq[uw + mb * 16 + g + 8];
    }

    // ---- ldmatrix lane constants (same permuted layout as R11) ----
    const int mtx   = lane >> 3;
    const int rrow  = lane & 7;
    const int h_l   = mtx >> 1;
    const int half  = mtx & 1;
    const int item1 = 4 * (rrow >> 1) + 2 * h_l + (rrow & 1);
    const int xsw   = ((item1 >> 3) & 1) << 1;
    const uint32_t sbase     = smem_u32(smem);
    const uint32_t lanebase1 = (uint32_t)(OF_I * 4) + (uint32_t)item1 * (PITCH * 4);

    // ---- cp.async staging constants: thread stages 32 B of one item row ----
    const int it_s = tid >> 3;                       // item row 0..31
    const int part = tid & 7;                        // 8-float part of the row
    const int xswr = ((it_s >> 3) & 1) << 1;         // chunk-XOR swizzle for this row
    const int sc0  = (2 * part) ^ xswr;              // dst chunk slots
    const int sc1  = (2 * part + 1) ^ xswr;
    const uint32_t dstrow = sbase + (uint32_t)(OF_I * 4) + (uint32_t)it_s * (PITCH * 4);

    const float4* items4 = reinterpret_cast<const float4*>(items);

    auto stage_async = [&](long tg, int b) {
        const float4* src = items4 + (tg * ITILE + it_s) * 16;
        const uint32_t d  = dstrow + (uint32_t)b * (IBUF * 4);
        CP_ASYNC16(d + sc0 * 16, src + 2 * part);
        CP_ASYNC16(d + sc1 * 16, src + 2 * part + 1);
        CP_COMMIT();
    };
    auto isq_compute = [&](int b) {
        // own cp.async data: visible to this thread after CP_WAIT0()
        const uint32_t d = dstrow + (uint32_t)b * (IBUF * 4);
        float x0, x1, x2, x3, y0, y1, y2, y3;
        asm volatile("ld.shared.v4.f32 {%0,%1,%2,%3}, [%4];"
                     : "=f"(x0), "=f"(x1), "=f"(x2), "=f"(x3) : "r"(d + sc0 * 16));
        asm volatile("ld.shared.v4.f32 {%0,%1,%2,%3}, [%4];"
                     : "=f"(y0), "=f"(y1), "=f"(y2), "=f"(y3) : "r"(d + sc1 * 16));
        float s = fmaf(x0, x0, fmaf(x1, x1, fmaf(x2, x2, x3 * x3)));
        s = fmaf(y0, y0, fmaf(y1, y1, fmaf(y2, y2, fmaf(y3, y3, s))));
        s += __shfl_xor_sync(0xffffffffu, s, 1);
        s += __shfl_xor_sync(0xffffffffu, s, 2);
        s += __shfl_xor_sync(0xffffffffu, s, 4);
        if (part == 0) smem[OF_ISQ + b * 32 + it_s] = s;
    };

    // ---- prologue: stage tile 0 into buffer 0 ----
    long tile = blockIdx.x;
    stage_async(tile, 0);
    CP_WAIT0();
    isq_compute(0);
    __syncthreads();

    int buf = 0;
    for (; tile < NTILES; tile += gridDim.x) {
        const long nt = tile + gridDim.x;

        // ---- kick next tile's async copies; they land during compute below ----
        if (nt < NTILES) stage_async(nt, buf ^ 1);

        float* isqB = smem + OF_ISQ + buf * 32;
        const uint32_t sI_l1 = sbase + lanebase1 + (uint32_t)buf * (IBUF * 4);
        const uint32_t sI_l2 = sI_l1 + 16u * (PITCH * 4);

        // ---- 32 users x 32 items per warp; A regs, B via ldmatrix.x4 ----
        float acc[2][4][4];
        #pragma unroll
        for (int mb = 0; mb < 2; mb++)
            #pragma unroll
            for (int nb = 0; nb < 4; nb++)
                #pragma unroll
                for (int q = 0; q < 4; q++) acc[mb][nb][q] = 0.f;

        #pragma unroll
        for (int kb = 0; kb < 8; kb++) {
            const uint32_t coff = (uint32_t)(((2 * kb + half) ^ xsw) * 16);
            uint32_t q[4];
            LDMX4(q, sI_l1 + coff);
            #pragma unroll
            for (int mb = 0; mb < 2; mb++) {
                asm volatile(
                    "mma.sync.aligned.m16n8k8.row.col.f32.tf32.tf32.f32 "
                    "{%0,%1,%2,%3}, {%4,%5,%6,%7}, {%8,%9}, {%0,%1,%2,%3};"
                    : "+f"(acc[mb][0][0]), "+f"(acc[mb][0][1]),
                      "+f"(acc[mb][0][2]), "+f"(acc[mb][0][3])
                    : "r"(Af[mb][kb][0]), "r"(Af[mb][kb][1]),
                      "r"(Af[mb][kb][2]), "r"(Af[mb][kb][3]), "r"(q[0]), "r"(q[1]));
                asm volatile(
                    "mma.sync.aligned.m16n8k8.row.col.f32.tf32.tf32.f32 "
                    "{%0,%1,%2,%3}, {%4,%5,%6,%7}, {%8,%9}, {%0,%1,%2,%3};"
                    : "+f"(acc[mb][1][0]), "+f"(acc[mb][1][1]),
                      "+f"(acc[mb][1][2]), "+f"(acc[mb][1][3])
                    : "r"(Af[mb][kb][0]), "r"(Af[mb][kb][1]),
                      "r"(Af[mb][kb][2]), "r"(Af[mb][kb][3]), "r"(q[2]), "r"(q[3]));
            }
            uint32_t s[4];
            LDMX4(s, sI_l2 + coff);
            #pragma unroll
            for (int mb = 0; mb < 2; mb++) {
                asm volatile(
                    "mma.sync.aligned.m16n8k8.row.col.f32.tf32.tf32.f32 "
                    "{%0,%1,%2,%3}, {%4,%5,%6,%7}, {%8,%9}, {%0,%1,%2,%3};"
                    : "+f"(acc[mb][2][0]), "+f"(acc[mb][2][1]),
                      "+f"(acc[mb][2][2]), "+f"(acc[mb][2][3])
                    : "r"(Af[mb][kb][0]), "r"(Af[mb][kb][1]),
                      "r"(Af[mb][kb][2]), "r"(Af[mb][kb][3]), "r"(s[0]), "r"(s[1]));
                asm volatile(
                    "mma.sync.aligned.m16n8k8.row.col.f32.tf32.tf32.f32 "
                    "{%0,%1,%2,%3}, {%4,%5,%6,%7}, {%8,%9}, {%0,%1,%2,%3};"
                    : "+f"(acc[mb][3][0]), "+f"(acc[mb][3][1]),
                      "+f"(acc[mb][3][2]), "+f"(acc[mb][3][3])
                    : "r"(Af[mb][kb][0]), "r"(Af[mb][kb][1]),
                      "r"(Af[mb][kb][2]), "r"(Af[mb][kb][3]), "r"(s[2]), "r"(s[3]));
            }
        }

        // ---- epilogue: thread holds items 4t..4t+3 per user row -> STG.128 (.cs) ----
        {
            const long ib = tile * ITILE;
            const float4 iqA  = *reinterpret_cast<const float4*>(isqB + 4 * t);
            const float4 iqB4 = *reinterpret_cast<const float4*>(isqB + 16 + 4 * t);
            #pragma unroll
            for (int mb = 0; mb < 2; mb++) {
                float* base0 = out + (size_t)(uw + mb * 16 + g) * kNItems + ib + 4 * t;
                #pragma unroll
                for (int p = 0; p < 2; p++) {
                    const float4 iq = p ? iqB4 : iqA;
                    const float* a0 = acc[mb][2 * p];
                    const float* a1 = acc[mb][2 * p + 1];
                    float4 v;
                    v.x = fmaf(2.f, a0[0], -(uqr[mb][0] + iq.x));
                    v.y = fmaf(2.f, a0[1], -(uqr[mb][0] + iq.y));
                    v.z = fmaf(2.f, a1[0], -(uqr[mb][0] + iq.z));
                    v.w = fmaf(2.f, a1[1], -(uqr[mb][0] + iq.w));
                    __stcs(reinterpret_cast<float4*>(base0 + p * 16), v);
                    float4 u;
                    u.x = fmaf(2.f, a0[2], -(uqr[mb][1] + iq.x));
                    u.y = fmaf(2.f, a0[3], -(uqr[mb][1] + iq.y));
                    u.z = fmaf(2.f, a1[2], -(uqr[mb][1] + iq.z));
                    u.w = fmaf(2.f, a1[3], -(uqr[mb][1] + iq.w));
                    __stcs(reinterpret_cast<float4*>(base0 + p * 16 + 8 * (size_t)kNItems), u);
                }
            }
        }

        // ---- retire async copies; own-data isq; single barrier per tile ----
        if (nt < NTILES) {
            CP_WAIT0();
            isq_compute(buf ^ 1);
        }
        __syncthreads();
        buf ^= 1;
    }
}

extern "C" void kernel_launch(void* const* d_in, const int* in_sizes, int n_in,
                              void* d_out, int out_size) {
    const int*   ids   = nullptr;
    const float* users = nullptr;
    const float* items = nullptr;
    for (int i = 0; i < n_in; i++) {
        if (in_sizes[i] == kNScore)              ids   = (const int*)d_in[i];
        else if (in_sizes[i] == kNUsers * kDim)  users = (const float*)d_in[i];
        else if (in_sizes[i] == kNItems * kDim)  items = (const float*)d_in[i];
    }
    cudaFuncSetAttribute(cml_kernel, cudaFuncAttributeMaxDynamicSharedMemorySize,
                         SMEM_BYTES);
    int sms = 0;
    if (cudaDeviceGetAttribute(&sms, cudaDevAttrMultiProcessorCount, 0) != cudaSuccess ||
        sms <= 0)
        sms = 148;
    cml_kernel<<<sms * 2, 256, SMEM_BYTES>>>(ids, users, items, (float*)d_out);
    (void)out_size;
}

// round 15
// speedup vs baseline: 1.0156x; 1.0156x over previous
#include <cuda_runtime.h>
#include <cuda_bf16.h>
#include <cstdint>

static constexpr int kNUsers = 100000;
static constexpr int kNItems = 500000;
static constexpr int kDim    = 64;
static constexpr int kNScore = 256;

static constexpr int ITILE  = 32;                    // 500000 % 32 == 0
static constexpr int NTILES = kNItems / ITILE;       // 15625 exact

// ---- SMEM byte layout ----
static constexpr unsigned OF_ISQ = 0;                // 2 x 32 floats (double buffered)
static constexpr unsigned OF_I   = 256;              // 2 x 32 rows x 128 B (bf16 items)
static constexpr unsigned IBUF_B = ITILE * 128;      // 4096 B per buffer
static constexpr unsigned SMEM_BYTES = OF_I + 2 * IBUF_B;   // 8448 B

__device__ __forceinline__ uint32_t smem_u32(const void* p) {
    return (uint32_t)__cvta_generic_to_shared(p);
}
__device__ __forceinline__ uint32_t pack_bf16x2(float lo, float hi) {
    uint32_t r;
    asm("cvt.rn.bf16x2.f32 %0, %1, %2;" : "=r"(r) : "f"(hi), "f"(lo));
    return r;
}
#define LDMX4(q, addr)                                                         \
    asm volatile("ldmatrix.sync.aligned.m8n8.x4.shared.b16 {%0,%1,%2,%3}, [%4];" \
                 : "=r"((q)[0]), "=r"((q)[1]), "=r"((q)[2]), "=r"((q)[3])      \
                 : "r"(addr))
#define MMA_BF16(acc, A, b0, b1)                                               \
    asm volatile(                                                              \
        "mma.sync.aligned.m16n8k16.row.col.f32.bf16.bf16.f32 "                 \
        "{%0,%1,%2,%3}, {%4,%5,%6,%7}, {%8,%9}, {%0,%1,%2,%3};"                \
        : "+f"((acc)[0]), "+f"((acc)[1]), "+f"((acc)[2]), "+f"((acc)[3])       \
        : "r"((A)[0]), "r"((A)[1]), "r"((A)[2]), "r"((A)[3]),                  \
          "r"(b0), "r"(b1))

__global__ void __launch_bounds__(256, 3)
cml_kernel(const int* __restrict__ ids,
           const float* __restrict__ users,
           const float* __restrict__ items,
           float* __restrict__ out)
{
    extern __shared__ __align__(128) char smem[];
    float* isq = reinterpret_cast<float*>(smem + OF_ISQ);
    const uint32_t sbase = smem_u32(smem);

    const int tid  = threadIdx.x;
    const int lane = tid & 31;
    const int w    = tid >> 5;    // warp id -> users w*32 .. w*32+31
    const int g    = lane >> 2;   // mma groupID
    const int t    = lane & 3;    // mma threadID-in-group
    const int uw   = w * 32;
    const int c    = tid & 15;    // staging chunk (4 floats) within 64-dim item row
    const int r0   = tid >> 4;    // staging item row (0..15)

    // ---- startup: gather this warp's 32 users global->registers (bf16 A frags)
    //      and exact fp32 row norms via in-quad shuffles. No user SMEM at all. ----
    uint32_t Af[2][4][4];
    float uqr[2][2];
    #pragma unroll
    for (int mb = 0; mb < 2; mb++) {
        const int u0 = ids[uw + mb * 16 + g];
        const int u1 = ids[uw + mb * 16 + 8 + g];
        const float* p0 = users + (size_t)u0 * kDim;
        const float* p1 = users + (size_t)u1 * kDim;
        float s0 = 0.f, s1 = 0.f;
        #pragma unroll
        for (int kb = 0; kb < 4; kb++) {
            #pragma unroll
            for (int hf = 0; hf < 2; hf++) {
                const int k = kb * 16 + hf * 8 + 2 * t;
                const float2 e0 = *reinterpret_cast<const float2*>(p0 + k);
                const float2 e1 = *reinterpret_cast<const float2*>(p1 + k);
                s0 = fmaf(e0.x, e0.x, fmaf(e0.y, e0.y, s0));
                s1 = fmaf(e1.x, e1.x, fmaf(e1.y, e1.y, s1));
                Af[mb][kb][hf * 2 + 0] = pack_bf16x2(e0.x, e0.y);  // row g
                Af[mb][kb][hf * 2 + 1] = pack_bf16x2(e1.x, e1.y);  // row g+8
            }
        }
        s0 += __shfl_xor_sync(0xffffffffu, s0, 1);
        s0 += __shfl_xor_sync(0xffffffffu, s0, 2);
        s1 += __shfl_xor_sync(0xffffffffu, s1, 1);
        s1 += __shfl_xor_sync(0xffffffffu, s1, 2);
        uqr[mb][0] = s0;
        uqr[mb][1] = s1;
    }

    // ---- ldmatrix lane constants ----
    // x4 matrices m: (nb = nbbase + (m>>1), khalf = m&1); lane supplies row (lane&7).
    const int sw   = lane & 7;                 // smrow&7 (row within nb block)
    const int khl  = (lane >> 3) & 1;
    const uint32_t rowA = (uint32_t)((lane >> 4) * 8 + sw) * 128u;  // nb 0/1 rows

    // ---- staging constants: thread stages items r0 and r0+16, chunk c ----
    // permuted SMEM row: smrow = p*16 + ((q>>1)&1)*8 + 2*(q>>2) + (q&1), q = r&15
    const int sm0  = (((r0 >> 1) & 1) << 3) + 2 * (r0 >> 2) + (r0 & 1);   // p=0
    const uint32_t stoff = (uint32_t)(sm0 * 128 + (((c >> 1) ^ (sm0 & 7)) * 16) + (c & 1) * 8);

    const float4* items4 = reinterpret_cast<const float4*>(items);

    auto stage = [&](float4 v0, float4 v1, int b) {
        // exact fp32 norms
        float s0 = fmaf(v0.x, v0.x, fmaf(v0.y, v0.y, fmaf(v0.z, v0.z, v0.w * v0.w)));
        float s1 = fmaf(v1.x, v1.x, fmaf(v1.y, v1.y, fmaf(v1.z, v1.z, v1.w * v1.w)));
        #pragma unroll
        for (int d = 1; d <= 8; d <<= 1) {
            s0 += __shfl_xor_sync(0xffffffffu, s0, d);
            s1 += __shfl_xor_sync(0xffffffffu, s1, d);
        }
        if (c == 0) {
            isq[b * 32 + r0]      = s0;
            isq[b * 32 + r0 + 16] = s1;
        }
        const uint32_t a = sbase + OF_I + (uint32_t)b * IBUF_B + stoff;
        const uint32_t w0 = pack_bf16x2(v0.x, v0.y), w1 = pack_bf16x2(v0.z, v0.w);
        const uint32_t w2 = pack_bf16x2(v1.x, v1.y), w3 = pack_bf16x2(v1.z, v1.w);
        asm volatile("st.shared.v2.b32 [%0], {%1,%2};" :: "r"(a), "r"(w0), "r"(w1) : "memory");
        asm volatile("st.shared.v2.b32 [%0], {%1,%2};"
                     :: "r"(a + 16u * 128u), "r"(w2), "r"(w3) : "memory");
    };

    // ---- prologue: stage tile 0 into buffer 0 ----
    long tile = blockIdx.x;
    {
        const long ib = tile * ITILE;
        float4 v0 = __ldcs(&items4[(ib + r0) * 16 + c]);
        float4 v1 = __ldcs(&items4[(ib + r0 + 16) * 16 + c]);
        stage(v0, v1, 0);
    }
    __syncthreads();

    int buf = 0;
    for (; tile < NTILES; tile += gridDim.x) {
        const long nt = tile + gridDim.x;

        // ---- issue next tile's LDGs; consumed after compute ----
        float4 npf0, npf1;
        if (nt < NTILES) {
            const long ib = nt * ITILE;
            npf0 = __ldcs(&items4[(ib + r0) * 16 + c]);
            npf1 = __ldcs(&items4[(ib + r0 + 16) * 16 + c]);
        }

        const uint32_t bb = sbase + OF_I + (uint32_t)buf * IBUF_B;
        float* isqB = isq + buf * 32;

        // ---- 32 users x 32 items per warp; A regs, B via ldmatrix.x4 bf16 ----
        float acc[2][4][4];
        #pragma unroll
        for (int mb = 0; mb < 2; mb++)
            #pragma unroll
            for (int nb = 0; nb < 4; nb++)
                #pragma unroll
                for (int q = 0; q < 4; q++) acc[mb][nb][q] = 0.f;

        #pragma unroll
        for (int kb = 0; kb < 4; kb++) {
            const uint32_t off = (uint32_t)(((2 * kb + khl) ^ sw) * 16);
            uint32_t q[4], s[4];
            LDMX4(q, bb + rowA + off);            // nb0: q0,q1 ; nb1: q2,q3
            LDMX4(s, bb + rowA + 2048u + off);    // nb2, nb3
            #pragma unroll
            for (int mb = 0; mb < 2; mb++) {
                MMA_BF16(acc[mb][0], Af[mb][kb], q[0], q[1]);
                MMA_BF16(acc[mb][1], Af[mb][kb], q[2], q[3]);
                MMA_BF16(acc[mb][2], Af[mb][kb], s[0], s[1]);
                MMA_BF16(acc[mb][3], Af[mb][kb], s[2], s[3]);
            }
        }

        // ---- epilogue: thread holds items 4t..4t+3 per user row -> STG.128 (.cs) ----
        {
            const long ib = tile * ITILE;
            const float4 iqA  = *reinterpret_cast<const float4*>(isqB + 4 * t);
            const float4 iqB4 = *reinterpret_cast<const float4*>(isqB + 16 + 4 * t);
            #pragma unroll
            for (int mb = 0; mb < 2; mb++) {
                float* base0 = out + (size_t)(uw + mb * 16 + g) * kNItems + ib + 4 * t;
                #pragma unroll
                for (int p = 0; p < 2; p++) {
                    const float4 iq = p ? iqB4 : iqA;
                    const float* a0 = acc[mb][2 * p];      // h=0: items 4t,4t+1
                    const float* a1 = acc[mb][2 * p + 1];  // h=1: items 4t+2,4t+3
                    float4 v;
                    v.x = fmaf(2.f, a0[0], -(uqr[mb][0] + iq.x));
                    v.y = fmaf(2.f, a0[1], -(uqr[mb][0] + iq.y));
                    v.z = fmaf(2.f, a1[0], -(uqr[mb][0] + iq.z));
                    v.w = fmaf(2.f, a1[1], -(uqr[mb][0] + iq.w));
                    __stcs(reinterpret_cast<float4*>(base0 + p * 16), v);
                    float4 u;
                    u.x = fmaf(2.f, a0[2], -(uqr[mb][1] + iq.x));
                    u.y = fmaf(2.f, a0[3], -(uqr[mb][1] + iq.y));
                    u.z = fmaf(2.f, a1[2], -(uqr[mb][1] + iq.z));
                    u.w = fmaf(2.f, a1[3], -(uqr[mb][1] + iq.w));
                    __stcs(reinterpret_cast<float4*>(base0 + p * 16 + 8 * (size_t)kNItems), u);
                }
            }
        }

        // ---- stage next tile into the other buffer; single barrier per tile ----
        if (nt < NTILES) stage(npf0, npf1, buf ^ 1);
        __syncthreads();
        buf ^= 1;
    }
}

extern "C" void kernel_launch(void* const* d_in, const int* in_sizes, int n_in,
                              void* d_out, int out_size) {
    const int*   ids   = nullptr;
    const float* users = nullptr;
    const float* items = nullptr;
    for (int i = 0; i < n_in; i++) {
        if (in_sizes[i] == kNScore)              ids   = (const int*)d_in[i];
        else if (in_sizes[i] == kNUsers * kDim)  users = (const float*)d_in[i];
        else if (in_sizes[i] == kNItems * kDim)  items = (const float*)d_in[i];
    }
    int sms = 0;
    if (cudaDeviceGetAttribute(&sms, cudaDevAttrMultiProcessorCount, 0) != cudaSuccess ||
        sms <= 0)
        sms = 148;
    cml_kernel<<<sms * 3, 256, SMEM_BYTES>>>(ids, users, items, (float*)d_out);
    (void)out_size;
}

// round 16
// speedup vs baseline: 1.0213x; 1.0056x over previous
#include <cuda_runtime.h>
#include <cstdint>

static constexpr int kNUsers = 100000;
static constexpr int kNItems = 500000;
static constexpr int kDim    = 64;
static constexpr int kNScore = 256;

static constexpr int ITILE  = 32;                    // 500000 % 32 == 0
static constexpr int NTILES = kNItems / ITILE;       // 15625 exact
static constexpr int PITCH  = 68;                    // floats per row; 272 B, 16B-aligned

// ---- SMEM layout (float offsets) ----
static constexpr int OF_USQ = 0;                     // 256
static constexpr int OF_ISQ = 256;                   // 2 x 32 (double buffered)
static constexpr int OF_U   = 320;                   // 256*68 (startup staging)
static constexpr int OF_I   = OF_U + 256 * PITCH;    // 17728
static constexpr int IBUF   = ITILE * PITCH;         // 2176 floats per buffer
static constexpr int SMEM_FLOATS = OF_I + 2 * IBUF;  // 22080
static constexpr unsigned SMEM_BYTES = SMEM_FLOATS * 4;   // 88320 -> 2 CTAs/SM

__device__ __forceinline__ uint32_t smem_u32(const void* p) {
    return (uint32_t)__cvta_generic_to_shared(p);
}
__device__ __forceinline__ uint32_t f2tf32(float x) {
    uint32_t r;
    asm("cvt.rna.tf32.f32 %0, %1;" : "=r"(r) : "f"(x));
    return r;
}
__device__ __forceinline__ float rsum16(float sq) {
    sq += __shfl_xor_sync(0xffffffffu, sq, 1);
    sq += __shfl_xor_sync(0xffffffffu, sq, 2);
    sq += __shfl_xor_sync(0xffffffffu, sq, 4);
    sq += __shfl_xor_sync(0xffffffffu, sq, 8);
    return sq;
}
#define LDMX4(q, addr)                                                         \
    asm volatile("ldmatrix.sync.aligned.m8n8.x4.shared.b16 {%0,%1,%2,%3}, [%4];" \
                 : "=r"((q)[0]), "=r"((q)[1]), "=r"((q)[2]), "=r"((q)[3])      \
                 : "r"(addr))

__global__ void __launch_bounds__(256, 2)
cml_kernel(const int* __restrict__ ids,
           const float* __restrict__ users,
           const float* __restrict__ items,
           float* __restrict__ out)
{
    extern __shared__ float smem[];
    float* usq = smem + OF_USQ;
    float* sU  = smem + OF_U;

    const int tid  = threadIdx.x;
    const int lane = tid & 31;
    const int w    = tid >> 5;    // warp id -> users w*32 .. w*32+31
    const int c    = tid & 15;    // float4 chunk within 64-dim row
    const int r0   = tid >> 4;    // staging row
    const int g    = lane >> 2;   // mma groupID
    const int t    = lane & 3;    // mma threadID-in-group
    const int uw   = w * 32;

    // ---- stage all 256 users: exact fp32 u_sq, rna-tf32 operand ----
    #pragma unroll
    for (int rr = 0; rr < 16; rr++) {
        const int r = r0 + rr * 16;
        const int uid = ids[r];
        float4 v = reinterpret_cast<const float4*>(users)[(size_t)uid * (kDim / 4) + c];
        float sq = rsum16(fmaf(v.x, v.x, fmaf(v.y, v.y, fmaf(v.z, v.z, v.w * v.w))));
        if (c == 0) usq[r] = sq;
        reinterpret_cast<uint4*>(sU + r * PITCH)[c] =
            make_uint4(f2tf32(v.x), f2tf32(v.y), f2tf32(v.z), f2tf32(v.w));
    }
    __syncthreads();

    // ---- hoist A fragments (this warp's 32 users, all k) into registers, forever ----
    uint32_t Af[2][8][4];
    #pragma unroll
    for (int mb = 0; mb < 2; mb++) {
        #pragma unroll
        for (int kb = 0; kb < 8; kb++) {
            const uint32_t* ap = reinterpret_cast<const uint32_t*>(
                sU + (uw + mb * 16 + g) * PITCH + kb * 8 + t);
            Af[mb][kb][0] = ap[0];
            Af[mb][kb][1] = ap[8 * PITCH];
            Af[mb][kb][2] = ap[4];
            Af[mb][kb][3] = ap[8 * PITCH + 4];
        }
    }
    float uqr[2][2];
    #pragma unroll
    for (int mb = 0; mb < 2; mb++) {
        uqr[mb][0] = usq[uw + mb * 16 + g];
        uqr[mb][1] = usq[uw + mb * 16 + g + 8];
    }

    // ---- ldmatrix lane constants (permuted layout, same as R11) ----
    const int mtx   = lane >> 3;
    const int rrow  = lane & 7;
    const int h_l   = mtx >> 1;
    const int half  = mtx & 1;
    const int item1 = 4 * (rrow >> 1) + 2 * h_l + (rrow & 1);
    const int xsw   = ((item1 >> 3) & 1) << 1;
    const uint32_t sbase     = smem_u32(smem);
    const uint32_t lanebase1 = (uint32_t)(OF_I * 4) + (uint32_t)item1 * (PITCH * 4);

    const float4* items4 = reinterpret_cast<const float4*>(items);

    // ---- CONTIGUOUS tile block per CTA (the R16 change) ----
    const long K  = (NTILES + gridDim.x - 1) / gridDim.x;
    const long t0 = (long)blockIdx.x * K;
    const long t1 = (t0 + K < (long)NTILES) ? t0 + K : (long)NTILES;

    // ---- prefetch + stage first tile into buffer 0 ----
    if (t0 < t1) {
        const long ib = t0 * ITILE;
        float4 p0 = __ldcs(&items4[(ib + r0) * 16 + c]);
        float4 p1 = __ldcs(&items4[(ib + r0 + 16) * 16 + c]);
        float* sIb  = smem + OF_I;
        float* isqB = smem + OF_ISQ;
        {
            float sq = rsum16(fmaf(p0.x, p0.x, fmaf(p0.y, p0.y, fmaf(p0.z, p0.z, p0.w * p0.w))));
            if (c == 0) isqB[r0] = sq;
            const int cc = c ^ (((r0 >> 3) & 1) << 1);
            reinterpret_cast<uint4*>(sIb + r0 * PITCH)[cc] =
                make_uint4(f2tf32(p0.x), f2tf32(p0.y), f2tf32(p0.z), f2tf32(p0.w));
        }
        {
            const int r = r0 + 16;
            float sq = rsum16(fmaf(p1.x, p1.x, fmaf(p1.y, p1.y, fmaf(p1.z, p1.z, p1.w * p1.w))));
            if (c == 0) isqB[r] = sq;
            const int cc = c ^ (((r >> 3) & 1) << 1);
            reinterpret_cast<uint4*>(sIb + r * PITCH)[cc] =
                make_uint4(f2tf32(p1.x), f2tf32(p1.y), f2tf32(p1.z), f2tf32(p1.w));
        }
    }
    __syncthreads();

    int buf = 0;
    for (long tile = t0; tile < t1; tile++) {
        const long nt = tile + 1;

        // ---- issue next tile's LDGs now; consumed after compute ----
        float4 npf0, npf1;
        if (nt < t1) {
            const long ib = nt * ITILE;
            npf0 = __ldcs(&items4[(ib + r0) * 16 + c]);
            npf1 = __ldcs(&items4[(ib + r0 + 16) * 16 + c]);
        }

        float* isqB = smem + OF_ISQ + buf * 32;
        const uint32_t sI_l1 = sbase + lanebase1 + (uint32_t)buf * (IBUF * 4);
        const uint32_t sI_l2 = sI_l1 + 16u * (PITCH * 4);

        // ---- 32 users x 32 items per warp; A regs, B via ldmatrix.x4 ----
        float acc[2][4][4];
        #pragma unroll
        for (int mb = 0; mb < 2; mb++)
            #pragma unroll
            for (int nb = 0; nb < 4; nb++)
                #pragma unroll
                for (int q = 0; q < 4; q++) acc[mb][nb][q] = 0.f;

        #pragma unroll
        for (int kb = 0; kb < 8; kb++) {
            const uint32_t coff = (uint32_t)(((2 * kb + half) ^ xsw) * 16);
            uint32_t q[4];
            LDMX4(q, sI_l1 + coff);
            #pragma unroll
            for (int mb = 0; mb < 2; mb++) {
                asm volatile(
                    "mma.sync.aligned.m16n8k8.row.col.f32.tf32.tf32.f32 "
                    "{%0,%1,%2,%3}, {%4,%5,%6,%7}, {%8,%9}, {%0,%1,%2,%3};"
                    : "+f"(acc[mb][0][0]), "+f"(acc[mb][0][1]),
                      "+f"(acc[mb][0][2]), "+f"(acc[mb][0][3])
                    : "r"(Af[mb][kb][0]), "r"(Af[mb][kb][1]),
                      "r"(Af[mb][kb][2]), "r"(Af[mb][kb][3]), "r"(q[0]), "r"(q[1]));
                asm volatile(
                    "mma.sync.aligned.m16n8k8.row.col.f32.tf32.tf32.f32 "
                    "{%0,%1,%2,%3}, {%4,%5,%6,%7}, {%8,%9}, {%0,%1,%2,%3};"
                    : "+f"(acc[mb][1][0]), "+f"(acc[mb][1][1]),
                      "+f"(acc[mb][1][2]), "+f"(acc[mb][1][3])
                    : "r"(Af[mb][kb][0]), "r"(Af[mb][kb][1]),
                      "r"(Af[mb][kb][2]), "r"(Af[mb][kb][3]), "r"(q[2]), "r"(q[3]));
            }
            uint32_t s[4];
            LDMX4(s, sI_l2 + coff);
            #pragma unroll
            for (int mb = 0; mb < 2; mb++) {
                asm volatile(
                    "mma.sync.aligned.m16n8k8.row.col.f32.tf32.tf32.f32 "
                    "{%0,%1,%2,%3}, {%4,%5,%6,%7}, {%8,%9}, {%0,%1,%2,%3};"
                    : "+f"(acc[mb][2][0]), "+f"(acc[mb][2][1]),
                      "+f"(acc[mb][2][2]), "+f"(acc[mb][2][3])
                    : "r"(Af[mb][kb][0]), "r"(Af[mb][kb][1]),
                      "r"(Af[mb][kb][2]), "r"(Af[mb][kb][3]), "r"(s[0]), "r"(s[1]));
                asm volatile(
                    "mma.sync.aligned.m16n8k8.row.col.f32.tf32.tf32.f32 "
                    "{%0,%1,%2,%3}, {%4,%5,%6,%7}, {%8,%9}, {%0,%1,%2,%3};"
                    : "+f"(acc[mb][3][0]), "+f"(acc[mb][3][1]),
                      "+f"(acc[mb][3][2]), "+f"(acc[mb][3][3])
                    : "r"(Af[mb][kb][0]), "r"(Af[mb][kb][1]),
                      "r"(Af[mb][kb][2]), "r"(Af[mb][kb][3]), "r"(s[2]), "r"(s[3]));
            }
        }

        // ---- epilogue: thread holds items 4t..4t+3 per user row -> STG.128 (.cs) ----
        {
            const long ib = tile * ITILE;
            const float4 iqA  = *reinterpret_cast<const float4*>(isqB + 4 * t);
            const float4 iqB4 = *reinterpret_cast<const float4*>(isqB + 16 + 4 * t);
            #pragma unroll
            for (int mb = 0; mb < 2; mb++) {
                float* base0 = out + (size_t)(uw + mb * 16 + g) * kNItems + ib + 4 * t;
                #pragma unroll
                for (int p = 0; p < 2; p++) {
                    const float4 iq = p ? iqB4 : iqA;
                    const float* a0 = acc[mb][2 * p];
                    const float* a1 = acc[mb][2 * p + 1];
                    float4 v;
                    v.x = fmaf(2.f, a0[0], -(uqr[mb][0] + iq.x));
                    v.y = fmaf(2.f, a0[1], -(uqr[mb][0] + iq.y));
                    v.z = fmaf(2.f, a1[0], -(uqr[mb][0] + iq.z));
                    v.w = fmaf(2.f, a1[1], -(uqr[mb][0] + iq.w));
                    __stcs(reinterpret_cast<float4*>(base0 + p * 16), v);
                    float4 u;
                    u.x = fmaf(2.f, a0[2], -(uqr[mb][1] + iq.x));
                    u.y = fmaf(2.f, a0[3], -(uqr[mb][1] + iq.y));
                    u.z = fmaf(2.f, a1[2], -(uqr[mb][1] + iq.z));
                    u.w = fmaf(2.f, a1[3], -(uqr[mb][1] + iq.w));
                    __stcs(reinterpret_cast<float4*>(base0 + p * 16 + 8 * (size_t)kNItems), u);
                }
            }
        }

        // ---- stage next tile into the other buffer; single sync per tile ----
        if (nt < t1) {
            float* sIn  = smem + OF_I + (buf ^ 1) * IBUF;
            float* isqN = smem + OF_ISQ + (buf ^ 1) * 32;
            {
                float sq = rsum16(fmaf(npf0.x, npf0.x, fmaf(npf0.y, npf0.y,
                                  fmaf(npf0.z, npf0.z, npf0.w * npf0.w))));
                if (c == 0) isqN[r0] = sq;
                const int cc = c ^ (((r0 >> 3) & 1) << 1);
                reinterpret_cast<uint4*>(sIn + r0 * PITCH)[cc] =
                    make_uint4(f2tf32(npf0.x), f2tf32(npf0.y), f2tf32(npf0.z), f2tf32(npf0.w));
            }
            {
                const int r = r0 + 16;
                float sq = rsum16(fmaf(npf1.x, npf1.x, fmaf(npf1.y, npf1.y,
                                  fmaf(npf1.z, npf1.z, npf1.w * npf1.w))));
                if (c == 0) isqN[r] = sq;
                const int cc = c ^ (((r >> 3) & 1) << 1);
                reinterpret_cast<uint4*>(sIn + r * PITCH)[cc] =
                    make_uint4(f2tf32(npf1.x), f2tf32(npf1.y), f2tf32(npf1.z), f2tf32(npf1.w));
            }
        }
        __syncthreads();
        buf ^= 1;
    }
}

extern "C" void kernel_launch(void* const* d_in, const int* in_sizes, int n_in,
                              void* d_out, int out_size) {
    const int*   ids   = nullptr;
    const float* users = nullptr;
    const float* items = nullptr;
    for (int i = 0; i < n_in; i++) {
        if (in_sizes[i] == kNScore)              ids   = (const int*)d_in[i];
        else if (in_sizes[i] == kNUsers * kDim)  users = (const float*)d_in[i];
        else if (in_sizes[i] == kNItems * kDim)  items = (const float*)d_in[i];
    }
    cudaFuncSetAttribute(cml_kernel, cudaFuncAttributeMaxDynamicSharedMemorySize,
                         SMEM_BYTES);
    int sms = 0;
    if (cudaDeviceGetAttribute(&sms, cudaDevAttrMultiProcessorCount, 0) != cudaSuccess ||
        sms <= 0)
        sms = 148;
    cml_kernel<<<sms * 2, 256, SMEM_BYTES>>>(ids, users, items, (float*)d_out);
    (void)out_size;
}

// round 17
// speedup vs baseline: 1.1124x; 1.0892x over previous
#include <cuda_runtime.h>
#include <cuda_bf16.h>
#include <cstdint>

static constexpr int kNUsers = 100000;
static constexpr int kNItems = 500000;
static constexpr int kDim    = 64;
static constexpr int kNScore = 256;

static constexpr int ITILE  = 32;                    // 500000 % 32 == 0
static constexpr int NTILES = kNItems / ITILE;       // 15625 exact

// ---- SMEM byte layout ----
static constexpr unsigned OF_ISQ = 0;                // 2 x 32 floats (double buffered)
static constexpr unsigned OF_I   = 256;              // 2 x 32 rows x 128 B (bf16 items)
static constexpr unsigned IBUF_B = ITILE * 128;      // 4096 B per buffer
static constexpr unsigned SMEM_BYTES = OF_I + 2 * IBUF_B;   // 8448 B

__device__ __forceinline__ uint32_t smem_u32(const void* p) {
    return (uint32_t)__cvta_generic_to_shared(p);
}
__device__ __forceinline__ uint32_t pack_bf16x2(float lo, float hi) {
    uint32_t r;
    asm("cvt.rn.bf16x2.f32 %0, %1, %2;" : "=r"(r) : "f"(hi), "f"(lo));
    return r;
}
#define LDMX4(q, addr)                                                         \
    asm volatile("ldmatrix.sync.aligned.m8n8.x4.shared.b16 {%0,%1,%2,%3}, [%4];" \
                 : "=r"((q)[0]), "=r"((q)[1]), "=r"((q)[2]), "=r"((q)[3])      \
                 : "r"(addr))
#define MMA_BF16(acc, A, b0, b1)                                               \
    asm volatile(                                                              \
        "mma.sync.aligned.m16n8k16.row.col.f32.bf16.bf16.f32 "                 \
        "{%0,%1,%2,%3}, {%4,%5,%6,%7}, {%8,%9}, {%0,%1,%2,%3};"                \
        : "+f"((acc)[0]), "+f"((acc)[1]), "+f"((acc)[2]), "+f"((acc)[3])       \
        : "r"((A)[0]), "r"((A)[1]), "r"((A)[2]), "r"((A)[3]),                  \
          "r"(b0), "r"(b1))

__global__ void __launch_bounds__(256, 2)
cml_kernel(const int* __restrict__ ids,
           const float* __restrict__ users,
           const float* __restrict__ items,
           float* __restrict__ out)
{
    extern __shared__ __align__(128) char smem[];
    float* isq = reinterpret_cast<float*>(smem + OF_ISQ);
    const uint32_t sbase = smem_u32(smem);

    const int tid  = threadIdx.x;
    const int lane = tid & 31;
    const int w    = tid >> 5;
    const int g    = lane >> 2;   // mma groupID
    const int t    = lane & 3;    // mma threadID-in-group
    const int uw   = (w & 3) * 64;        // this warp's 64-user slice
    const int iq   = (w >> 2) * 16;       // this warp's 16-item group within tile
    const int c    = tid & 15;    // staging chunk (4 floats) within 64-dim item row
    const int r0   = tid >> 4;    // staging local item (0..15); also stages r0+16

    // ---- startup: gather this warp's 64 users global->registers (bf16 A frags)
    //      and exact fp32 row norms via in-quad shuffles. ----
    uint32_t Af[4][4][4];
    float uqr[4][2];
    #pragma unroll
    for (int mb = 0; mb < 4; mb++) {
        const int u0 = ids[uw + mb * 16 + g];
        const int u1 = ids[uw + mb * 16 + 8 + g];
        const float* p0 = users + (size_t)u0 * kDim;
        const float* p1 = users + (size_t)u1 * kDim;
        float s0 = 0.f, s1 = 0.f;
        #pragma unroll
        for (int kb = 0; kb < 4; kb++) {
            #pragma unroll
            for (int hf = 0; hf < 2; hf++) {
                const int k = kb * 16 + hf * 8 + 2 * t;
                const float2 e0 = *reinterpret_cast<const float2*>(p0 + k);
                const float2 e1 = *reinterpret_cast<const float2*>(p1 + k);
                s0 = fmaf(e0.x, e0.x, fmaf(e0.y, e0.y, s0));
                s1 = fmaf(e1.x, e1.x, fmaf(e1.y, e1.y, s1));
                Af[mb][kb][hf * 2 + 0] = pack_bf16x2(e0.x, e0.y);  // row g
                Af[mb][kb][hf * 2 + 1] = pack_bf16x2(e1.x, e1.y);  // row g+8
            }
        }
        s0 += __shfl_xor_sync(0xffffffffu, s0, 1);
        s0 += __shfl_xor_sync(0xffffffffu, s0, 2);
        s1 += __shfl_xor_sync(0xffffffffu, s1, 1);
        s1 += __shfl_xor_sync(0xffffffffu, s1, 2);
        uqr[mb][0] = s0;
        uqr[mb][1] = s1;
    }

    // ---- ldmatrix lane constants ----
    // x4 matrices: m = lane>>3 -> nb = m>>1 (item parity), khalf = m&1.
    // SMEM row for (nb, mrow) = iq + nb*8 + mrow; column unit = (2kb+khalf)^mrow.
    const int mrow = lane & 7;
    const int khl  = (lane >> 3) & 1;
    const uint32_t rowbyte =
        (uint32_t)(iq + ((lane >> 4) & 1) * 8 + mrow) * 128u;

    // ---- staging constants ----
    // local item x -> smem row (x&1)*8 + (x>>1) within its 16-group.
    const int srow = (r0 & 1) * 8 + (r0 >> 1);
    const uint32_t stoff =
        (uint32_t)(srow * 128 + (((c >> 1) ^ (srow & 7)) * 16) + (c & 1) * 8);

    const float4* items4 = reinterpret_cast<const float4*>(items);

    auto stage = [&](float4 v0, float4 v1, int b) {
        // exact fp32 norms (items r0 and r0+16), reduced over the 16-thread chunk group
        float s0 = fmaf(v0.x, v0.x, fmaf(v0.y, v0.y, fmaf(v0.z, v0.z, v0.w * v0.w)));
        float s1 = fmaf(v1.x, v1.x, fmaf(v1.y, v1.y, fmaf(v1.z, v1.z, v1.w * v1.w)));
        #pragma unroll
        for (int d = 1; d <= 8; d <<= 1) {
            s0 += __shfl_xor_sync(0xffffffffu, s0, d);
            s1 += __shfl_xor_sync(0xffffffffu, s1, d);
        }
        if (c == 0) {
            isq[b * 32 + r0]      = s0;
            isq[b * 32 + r0 + 16] = s1;
        }
        const uint32_t a = sbase + OF_I + (uint32_t)b * IBUF_B + stoff;
        const uint32_t w0 = pack_bf16x2(v0.x, v0.y), w1 = pack_bf16x2(v0.z, v0.w);
        const uint32_t w2 = pack_bf16x2(v1.x, v1.y), w3 = pack_bf16x2(v1.z, v1.w);
        asm volatile("st.shared.v2.b32 [%0], {%1,%2};" :: "r"(a), "r"(w0), "r"(w1) : "memory");
        asm volatile("st.shared.v2.b32 [%0], {%1,%2};"
                     :: "r"(a + 16u * 128u), "r"(w2), "r"(w3) : "memory");
    };

    // ---- prologue: stage tile 0 into buffer 0 ----
    long tile = blockIdx.x;
    {
        const long ib = tile * ITILE;
        float4 v0 = __ldcs(&items4[(ib + r0) * 16 + c]);
        float4 v1 = __ldcs(&items4[(ib + r0 + 16) * 16 + c]);
        stage(v0, v1, 0);
    }
    __syncthreads();

    int buf = 0;
    for (; tile < NTILES; tile += gridDim.x) {
        const long nt = tile + gridDim.x;

        // ---- issue next tile's LDGs; consumed after compute ----
        float4 npf0, npf1;
        if (nt < NTILES) {
            const long ib = nt * ITILE;
            npf0 = __ldcs(&items4[(ib + r0) * 16 + c]);
            npf1 = __ldcs(&items4[(ib + r0 + 16) * 16 + c]);
        }

        const uint32_t bb = sbase + OF_I + (uint32_t)buf * IBUF_B;
        float* isqB = isq + buf * 32;

        // ---- 64 users x 16 items per warp; A regs, B via 1 ldmatrix.x4 per kb ----
        float acc[4][2][4];
        #pragma unroll
        for (int mb = 0; mb < 4; mb++)
            #pragma unroll
            for (int nb = 0; nb < 2; nb++)
                #pragma unroll
                for (int q = 0; q < 4; q++) acc[mb][nb][q] = 0.f;

        #pragma unroll
        for (int kb = 0; kb < 4; kb++) {
            const uint32_t off = (uint32_t)(((2 * kb + khl) ^ mrow) << 4);
            uint32_t q[4];
            LDMX4(q, bb + rowbyte + off);   // q0,q1 = nb0 (b0,b1); q2,q3 = nb1
            #pragma unroll
            for (int mb = 0; mb < 4; mb++) {
                MMA_BF16(acc[mb][0], Af[mb][kb], q[0], q[1]);
                MMA_BF16(acc[mb][1], Af[mb][kb], q[2], q[3]);
            }
        }

        // ---- epilogue: thread holds items iq+4t..4t+3 per user row -> STG.128 ----
        {
            const long ib = tile * ITILE;
            const float4 iqv = *reinterpret_cast<const float4*>(isqB + iq + 4 * t);
            #pragma unroll
            for (int mb = 0; mb < 4; mb++) {
                float* p0 = out + (size_t)(uw + mb * 16 + g) * kNItems + ib + iq + 4 * t;
                // row g: items 4t..4t+3 = {nb0.c2t, nb1.c2t, nb0.c2t+1, nb1.c2t+1}
                float4 v;
                v.x = fmaf(2.f, acc[mb][0][0], -(uqr[mb][0] + iqv.x));
                v.y = fmaf(2.f, acc[mb][1][0], -(uqr[mb][0] + iqv.y));
                v.z = fmaf(2.f, acc[mb][0][1], -(uqr[mb][0] + iqv.z));
                v.w = fmaf(2.f, acc[mb][1][1], -(uqr[mb][0] + iqv.w));
                __stcs(reinterpret_cast<float4*>(p0), v);
                float4 u;
                u.x = fmaf(2.f, acc[mb][0][2], -(uqr[mb][1] + iqv.x));
                u.y = fmaf(2.f, acc[mb][1][2], -(uqr[mb][1] + iqv.y));
                u.z = fmaf(2.f, acc[mb][0][3], -(uqr[mb][1] + iqv.z));
                u.w = fmaf(2.f, acc[mb][1][3], -(uqr[mb][1] + iqv.w));
                __stcs(reinterpret_cast<float4*>(p0 + 8 * (size_t)kNItems), u);
            }
        }

        // ---- stage next tile into the other buffer; single barrier per tile ----
        if (nt < NTILES) stage(npf0, npf1, buf ^ 1);
        __syncthreads();
        buf ^= 1;
    }
}

extern "C" void kernel_launch(void* const* d_in, const int* in_sizes, int n_in,
                              void* d_out, int out_size) {
    const int*   ids   = nullptr;
    const float* users = nullptr;
    const float* items = nullptr;
    for (int i = 0; i < n_in; i++) {
        if (in_sizes[i] == kNScore)              ids   = (const int*)d_in[i];
        else if (in_sizes[i] == kNUsers * kDim)  users = (const float*)d_in[i];
        else if (in_sizes[i] == kNItems * kDim)  items = (const float*)d_in[i];
    }
    int sms = 0;
    if (cudaDeviceGetAttribute(&sms, cudaDevAttrMultiProcessorCount, 0) != cudaSuccess ||
        sms <= 0)
        sms = 148;
    cml_kernel<<<sms * 2, 256, SMEM_BYTES>>>(ids, users, items, (float*)d_out);
    (void)out_size;
}